// round 9
// baseline (speedup 1.0000x reference)
#include <cuda_runtime.h>
#include <math.h>

#define LL 768
#define CS 256
#define CZ 128
#define NH 8
#define FEAT 544
#define NPROJ 1152
#define ATTN_OFF (LL*CS)

#define OFF_Q   0
#define OFF_K   256
#define OFF_V   512
#define OFF_QPL 768
#define OFF_KPL 864
#define OFF_VPL 960

typedef unsigned long long ull;

__device__ float g_sln[LL*CS];
__device__ float g_Wcat[CS*NPROJ];
__device__ float g_proj[LL*NPROJ];
__device__ float g_kt[CS*LL];            // [c][j]
__device__ float g_qpg[LL*96];           // [i][h*12+pp]
__device__ float g_kpgt[96*LL];          // [(h*12+pp)][j]
__device__ float g_vpg[LL*192];          // [j][h*24+pp]
__device__ float g_qn[LL*NH];
__device__ float g_knt[NH*LL];
__device__ float g_pb[(long)NH*LL*LL];   // [h][i][j]
__device__ float g_rs[(long)LL*LL];      // rstd per pair
__device__ float g_ms[(long)LL*LL];      // mean per pair
__device__ float g_feat[LL*FEAT];
__device__ float g_ptg[LL*192];
__device__ float g_T1[40];
__device__ float g_T0[40];
__device__ ull g_Wz[CZ*20];              // lnw-folded f32x2-packed z weights (40 cols)

__device__ __forceinline__ ull pk2(float lo, float hi){
    ull r; asm("mov.b64 %0,{%1,%2};":"=l"(r):"f"(lo),"f"(hi)); return r;
}
__device__ __forceinline__ void fma2(ull &d, ull a, ull b){
    asm("fma.rn.f32x2 %0, %1, %2, %0;" : "+l"(d) : "l"(a), "l"(b));
}
__device__ __forceinline__ float2 upk2(ull v){
    float2 r; asm("mov.b64 {%0,%1},%2;":"=f"(r.x),"=f"(r.y):"l"(v)); return r;
}

// ---- LN of s ----
__global__ __launch_bounds__(256) void k_ln_s(const float* __restrict__ s,
                                              const float* __restrict__ w,
                                              const float* __restrict__ b){
    int i = blockIdx.x, t = threadIdx.x;
    float x = s[i*CS + t];
    __shared__ float sh[8]; __shared__ float s_m, s_r;
    float v = x;
    #pragma unroll
    for (int o=16;o;o>>=1) v += __shfl_xor_sync(~0u,v,o);
    if ((t&31)==0) sh[t>>5]=v;
    __syncthreads();
    if (t==0){ float u=0; for(int kk=0;kk<8;kk++)u+=sh[kk]; s_m=u*(1.f/256.f); }
    __syncthreads();
    float d = x - s_m; v = d*d;
    #pragma unroll
    for (int o=16;o;o>>=1) v += __shfl_xor_sync(~0u,v,o);
    if ((t&31)==0) sh[t>>5]=v;
    __syncthreads();
    if (t==0){ float u=0; for(int kk=0;kk<8;kk++)u+=sh[kk]; s_r=rsqrtf(u*(1.f/256.f)+1e-5f); }
    __syncthreads();
    g_sln[i*CS+t] = d*s_r*w[t] + b[t];
}

// ---- premix: pack z-weights (lnw folded, f32x2) + T1/T0 fold constants ----
__global__ void k_premix(const float* __restrict__ lnw, const float* __restrict__ lnb,
                         const float* __restrict__ Wpb, const float* __restrict__ Wpo){
    int idx = blockIdx.x*256 + threadIdx.x;
    if (idx < 2560){
        int c = idx/20, np = idx%20, n = np*2;
        float w0 = lnw[c]*((n  <8)?Wpb[c*8+n  ]:Wpo[c*32+n-8]);
        float w1 = lnw[c]*((n+1<8)?Wpb[c*8+n+1]:Wpo[c*32+n-7]);
        g_Wz[idx] = pk2(w0,w1);
    } else if (idx < 2600){
        int n = idx-2560;
        float t1=0.f, t0=0.f;
        for(int c=0;c<CZ;c++){
            float wv = (n<8)?Wpb[c*8+n]:Wpo[c*32+n-8];
            t1 += lnw[c]*wv; t0 += lnb[c]*wv;
        }
        g_T1[n]=t1; g_T0[n]=t0;
    }
}

// ---- concat projection weights into [256][1152] ----
__global__ __launch_bounds__(256) void k_wcat(const float* __restrict__ Wq, const float* __restrict__ Wk,
                                              const float* __restrict__ Wv, const float* __restrict__ Wqp,
                                              const float* __restrict__ Wkp, const float* __restrict__ Wvp){
    int idx = blockIdx.x*256 + threadIdx.x;
    int k = idx/NPROJ, n = idx%NPROJ;
    float v;
    if      (n < 256)  v = Wq [k*256 + n];
    else if (n < 512)  v = Wk [k*256 + n-256];
    else if (n < 768)  v = Wv [k*256 + n-512];
    else if (n < 864)  v = Wqp[k*96  + n-768];
    else if (n < 960)  v = Wkp[k*96  + n-864];
    else               v = Wvp[k*192 + n-960];
    g_Wcat[idx] = v;
}

// ---- high-throughput SGEMM ----
__global__ __launch_bounds__(256) void k_sgemm2(const float* __restrict__ A,
                                                const float* __restrict__ W,
                                                const float* __restrict__ bias,
                                                const float* __restrict__ msk,
                                                float* __restrict__ C,
                                                int M, int N, int K){
    __shared__ float As[16][68], Bs[16][68];
    int tid = threadIdx.x;
    int tx = tid&15, ty = tid>>4;
    const float* Ab = A + (long)(blockIdx.y*64)*K;
    const float* Wb = W + blockIdx.x*64;
    float acc[4][4];
    #pragma unroll
    for(int u=0;u<4;u++)
        #pragma unroll
        for(int w2=0;w2<4;w2++) acc[u][w2]=0.f;

    int ar = tid>>2, ak = (tid&3)*4;
    int bk = tid>>4, bn = (tid&15)*4;
    float4 a4 = *(const float4*)&Ab[ar*K + ak];
    float4 b4 = *(const float4*)&Wb[(long)bk*N + bn];

    for(int k0=0;k0<K;k0+=16){
        As[ak+0][ar]=a4.x; As[ak+1][ar]=a4.y; As[ak+2][ar]=a4.z; As[ak+3][ar]=a4.w;
        *(float4*)&Bs[bk][bn]=b4;
        __syncthreads();
        if (k0+16 < K){
            a4 = *(const float4*)&Ab[ar*K + k0+16 + ak];
            b4 = *(const float4*)&Wb[(long)(k0+16+bk)*N + bn];
        }
        #pragma unroll
        for(int kk=0;kk<16;kk++){
            float4 av=*(const float4*)&As[kk][ty*4];
            float4 bv=*(const float4*)&Bs[kk][tx*4];
            float aa[4]={av.x,av.y,av.z,av.w};
            float bb[4]={bv.x,bv.y,bv.z,bv.w};
            #pragma unroll
            for(int u=0;u<4;u++)
                #pragma unroll
                for(int w2=0;w2<4;w2++) acc[u][w2] += aa[u]*bb[w2];
        }
        __syncthreads();
    }
    int gm0 = blockIdx.y*64 + ty*4, gn0 = blockIdx.x*64 + tx*4;
    #pragma unroll
    for(int u=0;u<4;u++){
        int gm = gm0+u;
        float mv = msk ? msk[gm] : 1.f;
        #pragma unroll
        for(int w2=0;w2<4;w2++){
            int gn = gn0+w2;
            float vv = acc[u][w2];
            if (bias) vv += bias[gn];
            C[(long)gm*N+gn] = vv*mv;
        }
    }
}

// ---- transpose k -> [c][j] ----
__global__ __launch_bounds__(256) void k_transpose_k(){
    __shared__ float tile[32][33];
    int c0=blockIdx.x*32, j0=blockIdx.y*32;
    int tx=threadIdx.x&31, ty=threadIdx.x>>5;
    for(int r=ty;r<32;r+=8) tile[r][tx]=g_proj[(j0+r)*NPROJ + OFF_K + c0+tx];
    __syncthreads();
    for(int r=ty;r<32;r+=8) g_kt[(c0+r)*LL+j0+tx]=tile[tx][r];
}

// ---- rigid transform of points + norms ----
__global__ __launch_bounds__(128) void k_transform(const float* __restrict__ R,
                                                   const float* __restrict__ t){
    int i=blockIdx.x, tid=threadIdx.x;
    __shared__ float Rl[9], tl[3];
    if(tid<9) Rl[tid]=R[i*9+tid];
    if(tid<3) tl[tid]=t[i*3+tid];
    __syncthreads();
    if (tid<32){
        const float* src = g_proj + i*NPROJ + OFF_QPL + tid*3;
        float p0=src[0], p1=src[1], p2=src[2];
        float gx=Rl[0]*p0+Rl[1]*p1+Rl[2]*p2+tl[0];
        float gy=Rl[3]*p0+Rl[4]*p1+Rl[5]*p2+tl[1];
        float gz=Rl[6]*p0+Rl[7]*p1+Rl[8]*p2+tl[2];
        g_qpg[i*96+tid*3]=gx; g_qpg[i*96+tid*3+1]=gy; g_qpg[i*96+tid*3+2]=gz;
        float sq=gx*gx+gy*gy+gz*gz;
        sq += __shfl_xor_sync(~0u,sq,1); sq += __shfl_xor_sync(~0u,sq,2);
        if((tid&3)==0) g_qn[i*NH+(tid>>2)]=sq;
    } else if (tid<64){
        int idx=tid-32;
        const float* src = g_proj + i*NPROJ + OFF_KPL + idx*3;
        float p0=src[0], p1=src[1], p2=src[2];
        float gx=Rl[0]*p0+Rl[1]*p1+Rl[2]*p2+tl[0];
        float gy=Rl[3]*p0+Rl[4]*p1+Rl[5]*p2+tl[1];
        float gz=Rl[6]*p0+Rl[7]*p1+Rl[8]*p2+tl[2];
        g_kpgt[(idx*3+0)*LL+i]=gx; g_kpgt[(idx*3+1)*LL+i]=gy; g_kpgt[(idx*3+2)*LL+i]=gz;
        float sq=gx*gx+gy*gy+gz*gz;
        sq += __shfl_xor_sync(~0u,sq,1); sq += __shfl_xor_sync(~0u,sq,2);
        if((idx&3)==0) g_knt[(idx>>2)*LL+i]=sq;
    } else {
        int idx=tid-64;
        const float* src = g_proj + i*NPROJ + OFF_VPL + idx*3;
        float p0=src[0], p1=src[1], p2=src[2];
        g_vpg[i*192+idx*3+0]=Rl[0]*p0+Rl[1]*p1+Rl[2]*p2+tl[0];
        g_vpg[i*192+idx*3+1]=Rl[3]*p0+Rl[4]*p1+Rl[5]*p2+tl[1];
        g_vpg[i*192+idx*3+2]=Rl[6]*p0+Rl[7]*p1+Rl[8]*p2+tl[2];
    }
}

// ---- z pass LITE: z read once -> mean/rstd + pair_bias (8 cols only) ----
__global__ __launch_bounds__(256) void k_zpassb(const float* __restrict__ z){
    __shared__ __align__(16) float Zs[16*264];
    __shared__ __align__(16) ull Ws[16][4];
    __shared__ float s_mean[256], s_rstd[256], T1s[8], T0s[8];
    int tid=threadIdx.x;
    long pair0=(long)blockIdx.x*256;
    int irow=(int)(pair0/LL), j0=(int)(pair0%LL);   // 256 | 768 -> tile within one i row
    if(tid<8){ T1s[tid]=g_T1[tid]; T0s[tid]=g_T0[tid]; }

    int rbase=(tid&63)*4, ty=tid>>6;
    ull acc[4]={0ull,0ull,0ull,0ull};

    int rq=tid>>2, kq=tid&3;
    float sums[4]={0,0,0,0}, sqs[4]={0,0,0,0};
    float4 pf[4];
    #pragma unroll
    for(int i=0;i<4;i++) pf[i]=*(const float4*)&z[(pair0+rq+64*i)*CZ + kq*4];

    for(int k0=0;k0<CZ;k0+=16){
        #pragma unroll
        for(int i=0;i<4;i++){
            float4 v=pf[i];
            sums[i]+=v.x+v.y+v.z+v.w;
            sqs[i]+=v.x*v.x+v.y*v.y+v.z*v.z+v.w*v.w;
            int row=rq+64*i, kkb=kq*4;
            Zs[(kkb+0)*264 + (row ^ (((kkb+0)&7)<<2))]=v.x;
            Zs[(kkb+1)*264 + (row ^ (((kkb+1)&7)<<2))]=v.y;
            Zs[(kkb+2)*264 + (row ^ (((kkb+2)&7)<<2))]=v.z;
            Zs[(kkb+3)*264 + (row ^ (((kkb+3)&7)<<2))]=v.w;
        }
        if(tid<64){ int kk=tid>>2, np=tid&3; Ws[kk][np]=g_Wz[(k0+kk)*20+np]; }
        __syncthreads();
        if(k0+16<CZ){
            #pragma unroll
            for(int i=0;i<4;i++) pf[i]=*(const float4*)&z[(pair0+rq+64*i)*CZ + k0+16 + kq*4];
        }
        #pragma unroll
        for(int kk=0;kk<16;kk++){
            float4 z4=*(const float4*)&Zs[kk*264 + (rbase ^ ((kk&7)<<2))];
            ull w=Ws[kk][ty];
            fma2(acc[0],pk2(z4.x,z4.x),w);
            fma2(acc[1],pk2(z4.y,z4.y),w);
            fma2(acc[2],pk2(z4.z,z4.z),w);
            fma2(acc[3],pk2(z4.w,z4.w),w);
        }
        __syncthreads();
    }
    #pragma unroll
    for(int i=0;i<4;i++){
        sums[i]+=__shfl_xor_sync(~0u,sums[i],1); sums[i]+=__shfl_xor_sync(~0u,sums[i],2);
        sqs[i] +=__shfl_xor_sync(~0u,sqs[i],1);  sqs[i] +=__shfl_xor_sync(~0u,sqs[i],2);
    }
    if(kq==0){
        #pragma unroll
        for(int i=0;i<4;i++){
            float m=sums[i]*(1.f/128.f);
            s_mean[rq+64*i]=m;
            s_rstd[rq+64*i]=rsqrtf(sqs[i]*(1.f/128.f)-m*m+1e-5f);
        }
    }
    __syncthreads();
    float o0[4], o1[4];
    int n0=ty*2;
    #pragma unroll
    for(int rr=0;rr<4;rr++){
        int r=rbase+rr;
        float rs=s_rstd[r], mn=s_mean[r];
        float2 a=upk2(acc[rr]);
        o0[rr]=rs*(a.x-mn*T1s[n0])  +T0s[n0];
        o1[rr]=rs*(a.y-mn*T1s[n0+1])+T0s[n0+1];
    }
    float4 v0={o0[0],o0[1],o0[2],o0[3]};
    float4 v1={o1[0],o1[1],o1[2],o1[3]};
    *(float4*)&g_pb[((long)n0*LL+irow)*LL + j0 + rbase]     = v0;
    *(float4*)&g_pb[((long)(n0+1)*LL+irow)*LL + j0 + rbase] = v1;
    g_rs[pair0+tid]=s_rstd[tid];
    g_ms[pair0+tid]=s_mean[tid];
}

// ---- fused logits + softmax -> attn (direct to d_out) ----
__global__ __launch_bounds__(256) void k_logits_softmax(const float* __restrict__ mask,
                                                        const float* __restrict__ pweights,
                                                        float* __restrict__ attn){
    int h=blockIdx.y, i0=blockIdx.x*4, tid=threadIdx.x;
    __shared__ float qv[4][32], qp[4][12], qnv[4], mi[4], red[8][4], bmax[4], brcp[4], s_pw;
    if(tid<128){ int ii=tid>>5, c=tid&31; qv[ii][c]=g_proj[(i0+ii)*NPROJ + OFF_Q + h*32+c]; }
    else if(tid<176){ int l=tid-128, ii=l/12, pp=l%12; qp[ii][pp]=g_qpg[(i0+ii)*96+h*12+pp]; }
    else if(tid<180){ int ii=tid-176; qnv[ii]=g_qn[(i0+ii)*NH+h]; mi[ii]=mask[i0+ii]; }
    else if(tid==180){ float xw=pweights[h]; s_pw=0.5f*log1pf(expf(xw)); }
    __syncthreads();

    float lv[3][4];
    const float invs = 0.17677669529663687f;
    #pragma unroll
    for(int jj=0;jj<3;jj++){
        int j=jj*256+tid;
        float sl[4]={0,0,0,0};
        const float* kt = g_kt + h*32*LL + j;
        #pragma unroll
        for(int c=0;c<32;c++){
            float kc=kt[c*LL];
            sl[0]+=qv[0][c]*kc; sl[1]+=qv[1][c]*kc; sl[2]+=qv[2][c]*kc; sl[3]+=qv[3][c]*kc;
        }
        float pd[4]={0,0,0,0};
        const float* kp = g_kpgt + h*12*LL + j;
        #pragma unroll
        for(int pp=0;pp<12;pp++){
            float kc=kp[pp*LL];
            pd[0]+=qp[0][pp]*kc; pd[1]+=qp[1][pp]*kc; pd[2]+=qp[2][pp]*kc; pd[3]+=qp[3][pp]*kc;
        }
        float knj=g_knt[h*LL+j], mj=mask[j];
        const float* pbp = g_pb + ((long)h*LL+i0)*LL + j;
        #pragma unroll
        for(int ii=0;ii<4;ii++){
            float lg = sl[ii]*invs + pbp[(long)ii*LL] - s_pw*(qnv[ii]+knj-2.f*pd[ii]);
            if (mi[ii]*mj==0.f) lg=-1e9f;
            lv[jj][ii]=lg;
        }
    }
    #pragma unroll
    for(int ii=0;ii<4;ii++){
        float m=fmaxf(fmaxf(lv[0][ii],lv[1][ii]),lv[2][ii]);
        #pragma unroll
        for(int o=16;o;o>>=1) m=fmaxf(m,__shfl_xor_sync(~0u,m,o));
        if((tid&31)==0) red[tid>>5][ii]=m;
    }
    __syncthreads();
    if(tid<4){ float m=red[0][tid]; for(int w=1;w<8;w++)m=fmaxf(m,red[w][tid]); bmax[tid]=m; }
    __syncthreads();
    float ev[3][4], sm[4]={0,0,0,0};
    #pragma unroll
    for(int jj=0;jj<3;jj++)
        #pragma unroll
        for(int ii=0;ii<4;ii++){ float e=__expf(lv[jj][ii]-bmax[ii]); ev[jj][ii]=e; sm[ii]+=e; }
    __syncthreads();
    #pragma unroll
    for(int ii=0;ii<4;ii++){
        float s=sm[ii];
        #pragma unroll
        for(int o=16;o;o>>=1) s+=__shfl_xor_sync(~0u,s,o);
        if((tid&31)==0) red[tid>>5][ii]=s;
    }
    __syncthreads();
    if(tid<4){ float s=0; for(int w=0;w<8;w++)s+=red[w][tid]; brcp[tid]=1.f/s; }
    __syncthreads();
    #pragma unroll
    for(int jj=0;jj<3;jj++){
        int j=jj*256+tid;
        #pragma unroll
        for(int ii=0;ii<4;ii++)
            attn[((long)h*LL+i0+ii)*LL+j]=ev[jj][ii]*brcp[ii];
    }
}

// ---- zattn: pair_out via reordered contraction (one block per i) ----
__global__ __launch_bounds__(256) void k_zattn(const float* __restrict__ z,
                                               const float* __restrict__ attn){
    __shared__ float ap[8*768];      // attn*rstd
    __shared__ float sW[128*33];     // lnw-folded pair_v weights [c][32]
    int i=blockIdx.x, tid=threadIdx.x;
    const float* fw = (const float*)g_Wz;
    for(int l=tid;l<4096;l+=256){
        int c=l>>5, o=l&31;
        sW[c*33+o]=fw[c*40+8+o];
    }
    for(int h=0;h<8;h++)
        for(int j=tid;j<LL;j+=256)
            ap[h*LL+j]=attn[((long)h*LL+i)*LL+j]*g_rs[(long)i*LL+j];
    __syncthreads();

    int cq=tid&31, hg=tid>>5;
    const float* zrow = z + (long)i*LL*CZ + cq*4;
    const float* aph = ap + hg*LL;
    ull acc01=0ull, acc23=0ull;
    #pragma unroll 4
    for(int j=0;j<LL;j++){
        float4 z4=*(const float4*)&zrow[j*CZ];
        float a=aph[j];
        ull as=pk2(a,a);
        fma2(acc01,as,pk2(z4.x,z4.y));
        fma2(acc23,as,pk2(z4.z,z4.w));
    }
    float2 f01=upk2(acc01), f23=upk2(acc23);
    float za[4]={f01.x,f01.y,f23.x,f23.y};
    // S_m = sum_j a'_j * m_j
    float smv=0.f;
    const float* mr = g_ms + (long)i*LL;
    for(int j=cq;j<LL;j+=32) smv += aph[j]*mr[j];
    // dots over this thread's 4 cols
    float pd[4]={0,0,0,0};
    int c0=cq*4;
    #pragma unroll
    for(int d=0;d<4;d++)
        #pragma unroll
        for(int u=0;u<4;u++)
            pd[d]+=sW[(c0+u)*33 + hg*4+d]*za[u];
    #pragma unroll
    for(int o=16;o;o>>=1){
        #pragma unroll
        for(int d=0;d<4;d++) pd[d]+=__shfl_xor_sync(~0u,pd[d],o);
        smv+=__shfl_xor_sync(~0u,smv,o);
    }
    if(cq==0){
        #pragma unroll
        for(int d=0;d<4;d++){
            int o=hg*4+d;
            g_feat[i*FEAT+512+o]=pd[d]-smv*g_T1[8+o]+g_T0[8+o];
        }
    }
}

// ---- fused attn @ [V | v_pts_global]: 56 output cols per head ----
__global__ __launch_bounds__(256) void k_attn_fused(const float* __restrict__ attn,
                                                    const float* __restrict__ V1,
                                                    const float* __restrict__ V2){
    int h=blockIdx.y, i0=blockIdx.x*16, tid=threadIdx.x;
    __shared__ float As[16][33], Vs[32][64];
    int n=tid&63, iw=tid>>6;
    float a0=0.f,a1=0.f,a2=0.f,a3=0.f;
    for(int j0=0;j0<LL;j0+=32){
        for(int l=tid;l<512;l+=256){
            int r=l>>5, jj=l&31;
            As[r][jj]=attn[((long)h*LL+i0+r)*LL+j0+jj];
        }
        for(int l=tid;l<2048;l+=256){
            int r=l>>6, c=l&63;
            float v;
            if (c<32)      v = V1[(long)(j0+r)*NPROJ + h*32 + c];
            else if (c<56) v = V2[(long)(j0+r)*192   + h*24 + (c-32)];
            else           v = 0.f;
            Vs[r][c]=v;
        }
        __syncthreads();
        #pragma unroll
        for(int jj=0;jj<32;jj++){
            float vv=Vs[jj][n];
            a0+=As[iw][jj]*vv; a1+=As[iw+4][jj]*vv;
            a2+=As[iw+8][jj]*vv; a3+=As[iw+12][jj]*vv;
        }
        __syncthreads();
    }
    if (n<32){
        g_feat[(i0+iw)   *FEAT + h*32+n]=a0;
        g_feat[(i0+iw+4) *FEAT + h*32+n]=a1;
        g_feat[(i0+iw+8) *FEAT + h*32+n]=a2;
        g_feat[(i0+iw+12)*FEAT + h*32+n]=a3;
    } else if (n<56){
        int c=n-32;
        g_ptg[(i0+iw)   *192 + h*24+c]=a0;
        g_ptg[(i0+iw+4) *192 + h*24+c]=a1;
        g_ptg[(i0+iw+8) *192 + h*24+c]=a2;
        g_ptg[(i0+iw+12)*192 + h*24+c]=a3;
    }
}

// ---- back to local frame + norms ----
__global__ __launch_bounds__(64) void k_local(const float* __restrict__ R,
                                              const float* __restrict__ t){
    int i=blockIdx.x, tid=threadIdx.x;
    __shared__ float Rl[9], tl[3];
    if(tid<9) Rl[tid]=R[i*9+tid];
    if(tid<3) tl[tid]=t[i*3+tid];
    __syncthreads();
    float gx=g_ptg[i*192+tid*3]  -tl[0];
    float gy=g_ptg[i*192+tid*3+1]-tl[1];
    float gz=g_ptg[i*192+tid*3+2]-tl[2];
    float lx=Rl[0]*gx+Rl[3]*gy+Rl[6]*gz;
    float ly=Rl[1]*gx+Rl[4]*gy+Rl[7]*gz;
    float lz=Rl[2]*gx+Rl[5]*gy+Rl[8]*gz;
    g_feat[i*FEAT+256+tid*3]  =lx;
    g_feat[i*FEAT+256+tid*3+1]=ly;
    g_feat[i*FEAT+256+tid*3+2]=lz;
    g_feat[i*FEAT+448+tid]=sqrtf(lx*lx+ly*ly+lz*lz+1e-8f);
}

extern "C" void kernel_launch(void* const* d_in, const int* in_sizes, int n_in,
                              void* d_out, int out_size){
    const float* s      =(const float*)d_in[0];
    const float* z      =(const float*)d_in[1];
    const float* R      =(const float*)d_in[2];
    const float* t      =(const float*)d_in[3];
    const float* mask   =(const float*)d_in[4];
    const float* ln_s_w =(const float*)d_in[5];
    const float* ln_s_b =(const float*)d_in[6];
    const float* ln_z_w =(const float*)d_in[7];
    const float* ln_z_b =(const float*)d_in[8];
    const float* Wq     =(const float*)d_in[9];
    const float* Wk     =(const float*)d_in[10];
    const float* Wv     =(const float*)d_in[11];
    const float* Wpb    =(const float*)d_in[12];
    const float* Wq_pts =(const float*)d_in[13];
    const float* Wk_pts =(const float*)d_in[14];
    const float* Wv_pts =(const float*)d_in[15];
    const float* pw     =(const float*)d_in[16];
    const float* Wpo    =(const float*)d_in[17];
    const float* W_out  =(const float*)d_in[18];
    const float* b_out  =(const float*)d_in[19];
    float* out  = (float*)d_out;
    float* attn = out + ATTN_OFF;

    float *p_sln,*p_wcat,*p_proj,*p_vpg,*p_feat;
    cudaGetSymbolAddress((void**)&p_sln,  g_sln);
    cudaGetSymbolAddress((void**)&p_wcat, g_Wcat);
    cudaGetSymbolAddress((void**)&p_proj, g_proj);
    cudaGetSymbolAddress((void**)&p_vpg,  g_vpg);
    cudaGetSymbolAddress((void**)&p_feat, g_feat);

    static cudaStream_t sB = nullptr;
    static cudaEvent_t evF1=nullptr, evJ1=nullptr, evF2=nullptr, evJ2=nullptr;
    if (sB == nullptr){
        cudaStreamCreateWithFlags(&sB, cudaStreamNonBlocking);
        cudaEventCreateWithFlags(&evF1, cudaEventDisableTiming);
        cudaEventCreateWithFlags(&evJ1, cudaEventDisableTiming);
        cudaEventCreateWithFlags(&evF2, cudaEventDisableTiming);
        cudaEventCreateWithFlags(&evJ2, cudaEventDisableTiming);
    }

    // fork 1: projection chain (sB) || z pass lite (s0)
    cudaEventRecord(evF1, 0);
    cudaStreamWaitEvent(sB, evF1, 0);

    k_ln_s<<<LL,256,0,sB>>>(s, ln_s_w, ln_s_b);
    k_wcat<<<(CS*NPROJ)/256,256,0,sB>>>(Wq, Wk, Wv, Wq_pts, Wk_pts, Wv_pts);
    k_sgemm2<<<dim3(NPROJ/64, LL/64),256,0,sB>>>(p_sln, p_wcat, nullptr, nullptr, p_proj, LL, NPROJ, CS);
    k_transpose_k<<<dim3(8,24),256,0,sB>>>();
    k_transform<<<LL,128,0,sB>>>(R, t);
    cudaEventRecord(evJ1, sB);

    k_premix<<<11,256>>>(ln_z_w, ln_z_b, Wpb, Wpo);
    k_zpassb<<<(LL*LL)/256,256>>>(z);

    cudaStreamWaitEvent(0, evJ1, 0);
    k_logits_softmax<<<dim3(LL/4,NH),256>>>(mask, pw, attn);

    // fork 2: attn_fused + local (sB) || zattn (s0)
    cudaEventRecord(evF2, 0);
    cudaStreamWaitEvent(sB, evF2, 0);
    k_attn_fused<<<dim3(LL/16,NH),256,0,sB>>>(attn, p_proj + OFF_V, p_vpg);
    k_local<<<LL,64,0,sB>>>(R, t);
    cudaEventRecord(evJ2, sB);

    k_zattn<<<LL,256>>>(z, attn);

    cudaStreamWaitEvent(0, evJ2, 0);
    k_sgemm2<<<dim3(CS/64, LL/64),256>>>(p_feat, W_out, b_out, mask, out, LL, CS, FEAT);
}